// round 15
// baseline (speedup 1.0000x reference)
#include <cuda_runtime.h>
#include <cuda_fp16.h>
#include <stdint.h>
#include <math.h>

// ---------------- problem constants ----------------
#define B_    4
#define NP_   512
#define PS_   16
#define D_    1024
#define NH_   4
#define HD_   256
#define PH_   4
#define KW_   5
#define T_    (B_*NP_*PS_)        // 32768 tokens
#define P_    (B_*NP_)            // 2048 patches
#define DD_   (D_*D_)
#define EPS_  1.1920929e-7f

// ---------------- device scratch ----------------
__device__ float g_x  [(size_t)T_*D_];
__device__ float g_t2 [(size_t)T_*D_];
__device__ float g_p0 [(size_t)P_*D_];
__device__ float g_p2 [(size_t)P_*D_];

// fp16 buffers
__device__ __half g_ah  [(size_t)T_*D_];
__device__ __half g_t1h [(size_t)T_*D_];
__device__ __half g_qkvh[(size_t)T_*3*D_];
__device__ __half g_wh[(size_t)9*DD_];
__device__ __half g_s1h[(size_t)P_*D_], g_s1l[(size_t)P_*D_];
__device__ __half g_s2h[(size_t)P_*D_], g_s2l[(size_t)P_*D_];

// ---------------- helpers ----------------
__device__ __forceinline__ uint32_t smem_u32(const void* p) {
    uint32_t a;
    asm("{ .reg .u64 t; cvta.to.shared.u64 t, %1; cvt.u32.u64 %0, t; }" : "=r"(a) : "l"(p));
    return a;
}
__device__ __forceinline__ void cvt_split_h(float x0, float x1,
                                            uint32_t& hw, uint32_t& lw) {
    uint32_t h;
    asm("cvt.rn.f16x2.f32 %0, %1, %2;" : "=r"(h) : "f"(x1), "f"(x0));
    __half2 hh = *reinterpret_cast<__half2*>(&h);
    float l0 = x0 - __half2float(__low2half(hh));
    float l1 = x1 - __half2float(__high2half(hh));
    asm("cvt.rn.f16x2.f32 %0, %1, %2;" : "=r"(lw) : "f"(l1), "f"(l0));
    hw = h;
}
__device__ __forceinline__ uint32_t cvt_h2(float x0, float x1) {
    uint32_t h;
    asm("cvt.rn.f16x2.f32 %0, %1, %2;" : "=r"(h) : "f"(x1), "f"(x0));
    return h;
}

#define MMA_F16(d, a, b) \
    asm volatile("mma.sync.aligned.m16n8k16.row.col.f32.f16.f16.f32 " \
        "{%0,%1,%2,%3},{%4,%5,%6,%7},{%8,%9},{%0,%1,%2,%3};" \
        : "+f"((d)[0]), "+f"((d)[1]), "+f"((d)[2]), "+f"((d)[3]) \
        : "r"((a)[0]), "r"((a)[1]), "r"((a)[2]), "r"((a)[3]), \
          "r"((b)[0]), "r"((b)[1]))

#define LDSM_X4(r, a) \
    asm volatile("ldmatrix.sync.aligned.m8n8.x4.shared.b16 {%0,%1,%2,%3}, [%4];" \
        : "=r"((r)[0]), "=r"((r)[1]), "=r"((r)[2]), "=r"((r)[3]) : "r"(a))

#define CP16(dst, src) \
    asm volatile("cp.async.cg.shared.global [%0], [%1], 16;" :: "r"(dst), "l"(src))
#define CP_COMMIT() asm volatile("cp.async.commit_group;" ::: "memory")
#define CP_WAIT(n)  asm volatile("cp.async.wait_group %0;" :: "n"(n) : "memory")
#define PF_L2(p)    asm volatile("prefetch.global.L2 [%0];" :: "l"(p))

// ================= fp16 split HMMA GEMM =================
// Tile 128x128, 256 thr (8 warps = 4m x 2n, warp tile 32x64), BK=32, 2 CTAs/SM.
// TERMS=1: 5-stage ring; TERMS=2: 3-stage ring. L2 prefetch for stage kt+NS.
#define BM_G 128
#define BN_G 128
#define BK_G 32
#define PITCH 80
#define SSZ_T1 ((BM_G + BN_G) * PITCH)        // 20480
#define SSZ_T2 ((2 * BM_G + BN_G) * PITCH)    // 30720
#define GEMM_SMEM_T1 (5 * SSZ_T1)             // 102400
#define GEMM_SMEM_T2 (3 * SSZ_T2)             // 92160

// EPI: 0=v; 1=silu(v); 2=v+aux(f32); 3=silu(aux f32)*v; 4=auxh(f16)*v.
// OUTM: 0 = f32 C; 1 = fp16 hi/lo planes; 2 = fp16 single.
template <int EPI, int OUTM, int TERMS>
__global__ __launch_bounds__(256, 2)
void hmma_gemm(int M, int N, int Kd,
               const __half* __restrict__ Ahp, const __half* __restrict__ Alp,
               const __half* __restrict__ Bhp,
               const float* __restrict__ aux, const __half* __restrict__ auxh,
               float* __restrict__ C,
               __half* __restrict__ Ch, __half* __restrict__ Cl) {
    constexpr int NS   = (TERMS == 1) ? 5 : 3;
    constexpr int WCAP = NS - 2;
    constexpr uint32_t ALO_OFF = BM_G * PITCH;
    constexpr uint32_t BHI_OFF = (uint32_t)TERMS * BM_G * PITCH;
    constexpr uint32_t SSZ = (uint32_t)(TERMS * BM_G + BN_G) * PITCH;

    extern __shared__ uint8_t sm[];
    const uint32_t sb = smem_u32(sm);
    const int tid = threadIdx.x;
    const int warp = tid >> 5, lane = tid & 31;
    const int qr = lane >> 2, qc = lane & 3;
    const int wm = warp & 3, wn = warp >> 2;
    const int bx = blockIdx.x, by = blockIdx.y;

    const __half* Ahg = Ahp + (size_t)(by * BM_G) * Kd;
    const __half* Alg = (TERMS == 2) ? (Alp + (size_t)(by * BM_G) * Kd) : nullptr;
    const __half* Bhg = Bhp + (size_t)(bx * BN_G) * Kd;

    float acc[2][8][4];
#pragma unroll
    for (int i = 0; i < 2; i++)
#pragma unroll
        for (int j = 0; j < 8; j++)
#pragma unroll
            for (int r = 0; r < 4; r++) acc[i][j][r] = 0.f;

    const int trow = tid >> 2, seg = tid & 3;
    const uint32_t aAddr = (uint32_t)(wm * 32 + (lane & 15)) * PITCH + (uint32_t)(lane >> 4) * 16;
    const uint32_t bAddr = (uint32_t)(wn * 64 + (lane & 7)) * PITCH + (uint32_t)(lane >> 3) * 16;

    auto ISSUE = [&](int kt) {
        const uint32_t st = sb + (uint32_t)(kt % NS) * SSZ;
        const int kb = kt * BK_G + seg * 8;
        const uint32_t o0 = (uint32_t)trow * PITCH + (uint32_t)seg * 16;
        const uint32_t o1 = o0 + 64u * PITCH;
        CP16(st + o0, Ahg + (size_t)trow * Kd + kb);
        CP16(st + o1, Ahg + (size_t)(trow + 64) * Kd + kb);
        if (TERMS == 2) {
            CP16(st + ALO_OFF + o0, Alg + (size_t)trow * Kd + kb);
            CP16(st + ALO_OFF + o1, Alg + (size_t)(trow + 64) * Kd + kb);
        }
        CP16(st + BHI_OFF + o0, Bhg + (size_t)trow * Kd + kb);
        CP16(st + BHI_OFF + o1, Bhg + (size_t)(trow + 64) * Kd + kb);
        CP_COMMIT();
        // L2 prefetch for the stage NS ahead (extends MLP past smem cap)
        const int kpf = (kt + NS) * BK_G + seg * 8;
        if (kpf < Kd) {
            PF_L2(Ahg + (size_t)trow * Kd + kpf);
            PF_L2(Ahg + (size_t)(trow + 64) * Kd + kpf);
            if (TERMS == 2) {
                PF_L2(Alg + (size_t)trow * Kd + kpf);
                PF_L2(Alg + (size_t)(trow + 64) * Kd + kpf);
            }
            PF_L2(Bhg + (size_t)trow * Kd + kpf);
            PF_L2(Bhg + (size_t)(trow + 64) * Kd + kpf);
        }
    };

    const int nk = Kd / BK_G;
#pragma unroll
    for (int s = 0; s < NS - 1; s++)
        if (s < nk) ISSUE(s);

    for (int kt = 0; kt < nk; kt++) {
        const int pend = nk - 1 - kt;
        if (pend >= WCAP) { CP_WAIT(WCAP); }
        else if (WCAP >= 3 && pend == 2) { CP_WAIT(2); }
        else if (pend == 1) { CP_WAIT(1); }
        else if (pend <= 0) { CP_WAIT(0); }
        else { CP_WAIT(1); }
        __syncthreads();
        if (kt + NS - 1 < nk) ISSUE(kt + NS - 1);

        const uint32_t st = sb + (uint32_t)(kt % NS) * SSZ;
        uint32_t bf[8][4];
#pragma unroll
        for (int nf = 0; nf < 8; nf++)
            LDSM_X4(bf[nf], st + BHI_OFF + bAddr + (uint32_t)nf * (8 * PITCH));
#pragma unroll
        for (int ks = 0; ks < 2; ks++) {
            uint32_t ah[2][4], al[2][4];
#pragma unroll
            for (int mf = 0; mf < 2; mf++) {
                const uint32_t a = st + aAddr + (uint32_t)mf * (16 * PITCH) + (uint32_t)ks * 32;
                LDSM_X4(ah[mf], a);
                if (TERMS == 2) LDSM_X4(al[mf], a + ALO_OFF);
            }
#pragma unroll
            for (int nf = 0; nf < 8; nf++) {
#pragma unroll
                for (int mf = 0; mf < 2; mf++) {
                    MMA_F16(acc[mf][nf], ah[mf], &bf[nf][2 * ks]);
                    if (TERMS == 2) MMA_F16(acc[mf][nf], al[mf], &bf[nf][2 * ks]);
                }
            }
        }
    }

    // ---- epilogue ----
    const int row0 = by * BM_G + wm * 32;
    const int col0 = bx * BN_G + wn * 64;
#pragma unroll
    for (int mf = 0; mf < 2; mf++) {
#pragma unroll
        for (int nf = 0; nf < 8; nf++) {
            const int r = row0 + mf * 16 + qr;
            const int c = col0 + nf * 8 + qc * 2;
            float v0 = acc[mf][nf][0], v1 = acc[mf][nf][1];
            float v2 = acc[mf][nf][2], v3 = acc[mf][nf][3];
            if (EPI == 1) {
                v0 = v0 / (1.f + __expf(-v0)); v1 = v1 / (1.f + __expf(-v1));
                v2 = v2 / (1.f + __expf(-v2)); v3 = v3 / (1.f + __expf(-v3));
            }
            if (EPI == 2) {
                const float* a0 = aux + (size_t)r * N + c;
                const float* a1 = aux + (size_t)(r + 8) * N + c;
                v0 += a0[0]; v1 += a0[1]; v2 += a1[0]; v3 += a1[1];
            }
            if (EPI == 3) {
                const float* a0 = aux + (size_t)r * N + c;
                const float* a1 = aux + (size_t)(r + 8) * N + c;
                float g0 = a0[0], g1 = a0[1], g2 = a1[0], g3 = a1[1];
                v0 *= g0 / (1.f + __expf(-g0)); v1 *= g1 / (1.f + __expf(-g1));
                v2 *= g2 / (1.f + __expf(-g2)); v3 *= g3 / (1.f + __expf(-g3));
            }
            if (EPI == 4) {
                __half2 a0 = *(const __half2*)(auxh + (size_t)r * N + c);
                __half2 a1 = *(const __half2*)(auxh + (size_t)(r + 8) * N + c);
                v0 *= __half2float(__low2half(a0)); v1 *= __half2float(__high2half(a0));
                v2 *= __half2float(__low2half(a1)); v3 *= __half2float(__high2half(a1));
            }
            if (OUTM == 0) {
                *(float2*)(C + (size_t)r * N + c) = make_float2(v0, v1);
                *(float2*)(C + (size_t)(r + 8) * N + c) = make_float2(v2, v3);
            } else if (OUTM == 1) {
                uint32_t hw, lw;
                cvt_split_h(v0, v1, hw, lw);
                *(uint32_t*)(Ch + (size_t)r * N + c) = hw;
                *(uint32_t*)(Cl + (size_t)r * N + c) = lw;
                cvt_split_h(v2, v3, hw, lw);
                *(uint32_t*)(Ch + (size_t)(r + 8) * N + c) = hw;
                *(uint32_t*)(Cl + (size_t)(r + 8) * N + c) = lw;
            } else {
                *(uint32_t*)(Ch + (size_t)r * N + c) = cvt_h2(v0, v1);
                *(uint32_t*)(Ch + (size_t)(r + 8) * N + c) = cvt_h2(v2, v3);
            }
        }
    }
}

// ================= aux kernels =================
__device__ __forceinline__ float warp_sum(float v) {
#pragma unroll
    for (int o = 16; o; o >>= 1) v += __shfl_down_sync(0xffffffffu, v, o);
    return v;
}
__device__ __forceinline__ float block_sum_256(float v, float* red) {
    int lane = threadIdx.x & 31, w = threadIdx.x >> 5;
    v = warp_sum(v);
    if (lane == 0) red[w] = v;
    __syncthreads();
    if (w == 0) {
        float x = (lane < 8) ? red[lane] : 0.f;
        x = warp_sum(x);
        if (lane == 0) red[0] = x;
    }
    __syncthreads();
    return red[0];
}

__global__ void k_split_all(const float* __restrict__ wg, const float* __restrict__ wi,
                            const float* __restrict__ wq, const float* __restrict__ wm,
                            const float* __restrict__ wu, const float* __restrict__ wd,
                            const float* __restrict__ wo, __half* __restrict__ wh) {
    const int y = blockIdx.y;
    const float* src;
    if      (y == 0) src = wg;
    else if (y == 1) src = wi;
    else if (y <  5) src = wq + (size_t)(y - 2) * DD_;
    else if (y == 5) src = wm;
    else if (y == 6) src = wu;
    else if (y == 7) src = wd;
    else             src = wo;
    const size_t base = (size_t)y * DD_;
    const int i = blockIdx.x * blockDim.x + threadIdx.x;
    float4 v = ((const float4*)src)[i];
    ((uint2*)(wh + base))[i] = make_uint2(cvt_h2(v.x, v.y), cvt_h2(v.z, v.w));
}

__global__ void k_add_pos_norm_h1(const float* __restrict__ x,
                                  const float* __restrict__ pos,
                                  __half* __restrict__ oh) {
    __shared__ float red[8];
    int row = blockIdx.x, t = threadIdx.x;
    float4 a = ((const float4*)(x + (size_t)row * D_))[t];
    float4 b = ((const float4*)(pos + (size_t)(row & (PS_ - 1)) * D_))[t];
    a.x += b.x; a.y += b.y; a.z += b.z; a.w += b.w;
    float tot = block_sum_256(a.x*a.x + a.y*a.y + a.z*a.z + a.w*a.w, red);
    float s = rsqrtf(tot * (1.0f / D_) + EPS_);
    ((uint2*)(oh + (size_t)row * D_))[t] =
        make_uint2(cvt_h2(a.x * s, a.y * s), cvt_h2(a.z * s, a.w * s));
}

__global__ void k_rmsnorm_h(const float* __restrict__ x,
                            __half* __restrict__ oh, __half* __restrict__ ol) {
    __shared__ float red[8];
    int row = blockIdx.x, t = threadIdx.x;
    float4 a = ((const float4*)(x + (size_t)row * D_))[t];
    float tot = block_sum_256(a.x*a.x + a.y*a.y + a.z*a.z + a.w*a.w, red);
    float s = rsqrtf(tot * (1.0f / D_) + EPS_);
    uint32_t h0, l0, h1, l1;
    cvt_split_h(a.x * s, a.y * s, h0, l0);
    cvt_split_h(a.z * s, a.w * s, h1, l1);
    ((uint2*)(oh + (size_t)row * D_))[t] = make_uint2(h0, h1);
    ((uint2*)(ol + (size_t)row * D_))[t] = make_uint2(l0, l1);
}

__global__ void k_rmsnorm(const float* __restrict__ x, float* __restrict__ out) {
    __shared__ float red[8];
    int row = blockIdx.x, t = threadIdx.x;
    float4 a = ((const float4*)(x + (size_t)row * D_))[t];
    float tot = block_sum_256(a.x*a.x + a.y*a.y + a.z*a.z + a.w*a.w, red);
    float s = rsqrtf(tot * (1.0f / D_) + EPS_);
    ((float4*)(out + (size_t)row * D_))[t] = make_float4(a.x*s, a.y*s, a.z*s, a.w*s);
}

// fused depthwise conv + residual + rmsnorm: block = patch, 1024 thr (1/channel)
__global__ __launch_bounds__(1024, 1)
void k_conv_norm(float* __restrict__ x, const float* __restrict__ w,
                 __half* __restrict__ oh) {
    __shared__ float red[PS_][33];
    __shared__ float sscale[PS_];
    const int patch = blockIdx.x, c = threadIdx.x;
    const int lane = c & 31, wid = c >> 5;

    float wk[KW_];
#pragma unroll
    for (int k = 0; k < KW_; k++) wk[k] = w[c * KW_ + k];
    const size_t base = (size_t)patch * PS_ * D_ + c;
    float v[PS_], o[PS_];
#pragma unroll
    for (int p = 0; p < PS_; p++) v[p] = x[base + (size_t)p * D_];
#pragma unroll
    for (int p = 0; p < PS_; p++) {
        float acc = v[p];
#pragma unroll
        for (int k = 0; k < KW_; k++) {
            int src = p + k - (KW_ - 1);
            if (src >= 0) acc += v[src] * wk[k];
        }
        o[p] = acc;
        x[base + (size_t)p * D_] = acc;          // residual stream (fp32)
    }
    // row-wise sum of squares across 1024 channels
#pragma unroll
    for (int p = 0; p < PS_; p++) {
        float s = warp_sum(o[p] * o[p]);
        if (lane == 0) red[p][wid] = s;
    }
    __syncthreads();
    if (wid < PS_) {
        float s = warp_sum(red[wid][lane]);
        if (lane == 0) sscale[wid] = rsqrtf(s * (1.0f / D_) + EPS_);
    }
    __syncthreads();
#pragma unroll
    for (int p = 0; p < PS_; p++)
        oh[base + (size_t)p * D_] = __float2half(o[p] * sscale[p]);
}

// attention; fp16 qkv in, fp16 hi plane out
__global__ void k_attn(const __half* __restrict__ qkv, __half* __restrict__ oh) {
    __shared__ float bufA[PS_ * HD_];
    __shared__ float bufK[HD_ * (PS_ + 1)];
    __shared__ float S[PS_][PS_ + 1];
    int patch = blockIdx.x, h = blockIdx.y, t = threadIdx.x;

    for (int i = t; i < PS_ * HD_; i += 256) {
        int p = i >> 8, d = i & (HD_ - 1);
        size_t base = ((size_t)(patch * PS_ + p)) * (3 * D_) + (size_t)h * HD_;
        bufA[p * HD_ + d] = __half2float(qkv[base + d]);
        bufK[d * (PS_ + 1) + p] = __half2float(qkv[base + D_ + d]);
    }
    __syncthreads();
    {
        int i = t >> 4, j = t & 15;
        float acc = 0.f;
#pragma unroll 8
        for (int d = 0; d < HD_; d++)
            acc += bufA[i * HD_ + d] * bufK[d * (PS_ + 1) + j];
        S[i][j] = acc * 0.0625f;
    }
    __syncthreads();
    for (int i = t; i < PS_ * HD_; i += 256) {
        int p = i >> 8, d = i & (HD_ - 1);
        size_t base = ((size_t)(patch * PS_ + p)) * (3 * D_) + (size_t)h * HD_;
        bufA[p * HD_ + d] = __half2float(qkv[base + 2 * D_ + d]);
    }
    if (t < PS_) {
        float lv[PS_], m = -1e30f;
#pragma unroll
        for (int j = 0; j < PS_; j++) { lv[j] = S[t][j]; m = fmaxf(m, lv[j]); }
        float s = 0.f;
#pragma unroll
        for (int j = 0; j < PS_; j++) { lv[j] = __expf(lv[j] - m); s += lv[j]; }
        float inv = 1.f / s;
#pragma unroll
        for (int j = 0; j < PS_; j++) S[t][j] = lv[j] * inv;
    }
    __syncthreads();
    {
        int i = t >> 4, dc = t & 15;
        float acc[16];
#pragma unroll
        for (int r = 0; r < 16; r++) acc[r] = 0.f;
#pragma unroll
        for (int j = 0; j < PS_; j++) {
            float s = S[i][j];
#pragma unroll
            for (int r = 0; r < 16; r++)
                acc[r] += s * bufA[j * HD_ + dc * 16 + r];
        }
        size_t ob = ((size_t)(patch * PS_ + i)) * D_ + (size_t)h * HD_ + dc * 16;
        uint32_t hw[8];
#pragma unroll
        for (int p = 0; p < 8; p++) hw[p] = cvt_h2(acc[2*p], acc[2*p+1]);
        ((uint4*)(oh + ob))[0] = make_uint4(hw[0], hw[1], hw[2], hw[3]);
        ((uint4*)(oh + ob))[1] = make_uint4(hw[4], hw[5], hw[6], hw[7]);
    }
}

// fused rmsnorm + attention pooling
#define POOLF_SMEM ((PS_*D_ + PH_*D_ + PS_ + PH_*PS_ + 32) * 4)
__global__ __launch_bounds__(256, 2)
void k_pool_f(const float* __restrict__ x4, const float* __restrict__ wpool,
              const float* __restrict__ temp, float* __restrict__ out) {
    extern __shared__ float psm[];
    float* sx   = psm;
    float* swp  = sx + PS_ * D_;
    float* srow = swp + PH_ * D_;
    float* slog = srow + PS_;
    int patch = blockIdx.x, t = threadIdx.x;
    int w = t >> 5, lane = t & 31;

#pragma unroll
    for (int rr = 0; rr < 2; rr++) {
        int p = w * 2 + rr;
        const float4* src = (const float4*)(x4 + ((size_t)patch * PS_ + p) * D_);
        float ss = 0.f;
#pragma unroll
        for (int i = 0; i < 8; i++) {
            float4 v = src[lane + 32 * i];
            ((float4*)(sx + p * D_))[lane + 32 * i] = v;
            ss += v.x*v.x + v.y*v.y + v.z*v.z + v.w*v.w;
        }
        ss = warp_sum(ss);
        if (lane == 0) srow[p] = rsqrtf(ss * (1.0f / D_) + EPS_);
    }
    for (int i = t; i < PH_ * D_; i += 256) swp[i] = wpool[i];
    __syncthreads();

    for (int p = w; p < PS_; p += 8) {
        const float* xr = sx + p * D_;
        float a0 = 0, a1 = 0, a2 = 0, a3 = 0;
        for (int d = lane; d < D_; d += 32) {
            float xv = xr[d];
            a0 += xv * swp[d];
            a1 += xv * swp[D_ + d];
            a2 += xv * swp[2 * D_ + d];
            a3 += xv * swp[3 * D_ + d];
        }
        a0 = warp_sum(a0); a1 = warp_sum(a1); a2 = warp_sum(a2); a3 = warp_sum(a3);
        if (lane == 0) {
            float s = srow[p];
            slog[0 * PS_ + p] = a0 * s; slog[1 * PS_ + p] = a1 * s;
            slog[2 * PS_ + p] = a2 * s; slog[3 * PS_ + p] = a3 * s;
        }
    }
    __syncthreads();
    if (t < PH_) {
        float inv = 1.f / fmaxf(temp[0], 0.01f);
        float lv[PS_], m = -1e30f;
#pragma unroll
        for (int p = 0; p < PS_; p++) { lv[p] = slog[t * PS_ + p] * inv; m = fmaxf(m, lv[p]); }
        float s = 0.f;
#pragma unroll
        for (int p = 0; p < PS_; p++) { lv[p] = __expf(lv[p] - m); s += lv[p]; }
        float is = 1.f / s;
#pragma unroll
        for (int p = 0; p < PS_; p++) slog[t * PS_ + p] = lv[p] * is;
    }
    __syncthreads();
    int dd = t * 4;
    int h = dd >> 8;
    float4 acc = make_float4(0, 0, 0, 0);
#pragma unroll
    for (int p = 0; p < PS_; p++) {
        float wg = slog[h * PS_ + p] * srow[p];
        float4 xv = *(const float4*)(sx + p * D_ + dd);
        acc.x += wg * xv.x; acc.y += wg * xv.y; acc.z += wg * xv.z; acc.w += wg * xv.w;
    }
    *(float4*)(out + (size_t)patch * D_ + dd) = acc;
}

// ================= launch =================
extern "C" void kernel_launch(void* const* d_in, const int* in_sizes, int n_in,
                              void* d_out, int out_size) {
    const float* patch   = (const float*)d_in[0];
    const float* pos     = (const float*)d_in[1];
    const float* w_gate  = (const float*)d_in[2];
    const float* w_in    = (const float*)d_in[3];
    const float* conv_w  = (const float*)d_in[4];
    const float* w_qkv   = (const float*)d_in[5];
    const float* w_intra = (const float*)d_in[6];
    const float* w_pool  = (const float*)d_in[7];
    const float* temp    = (const float*)d_in[8];
    const float* w_up    = (const float*)d_in[9];
    const float* w_down  = (const float*)d_in[10];
    const float* w_out   = (const float*)d_in[11];
    float* out = (float*)d_out;

    float *p_x, *p_t2, *p_p0, *p_p2;
    cudaGetSymbolAddress((void**)&p_x,   g_x);
    cudaGetSymbolAddress((void**)&p_t2,  g_t2);
    cudaGetSymbolAddress((void**)&p_p0,  g_p0);
    cudaGetSymbolAddress((void**)&p_p2,  g_p2);

    __half *ah, *t1h, *qkvh, *wh, *s1h, *s1l, *s2h, *s2l;
    cudaGetSymbolAddress((void**)&ah,   g_ah);
    cudaGetSymbolAddress((void**)&t1h,  g_t1h);
    cudaGetSymbolAddress((void**)&qkvh, g_qkvh);
    cudaGetSymbolAddress((void**)&wh,   g_wh);
    cudaGetSymbolAddress((void**)&s1h, g_s1h); cudaGetSymbolAddress((void**)&s1l, g_s1l);
    cudaGetSymbolAddress((void**)&s2h, g_s2h); cudaGetSymbolAddress((void**)&s2l, g_s2l);

    cudaFuncSetAttribute(hmma_gemm<1,2,1>, cudaFuncAttributeMaxDynamicSharedMemorySize, GEMM_SMEM_T1);
    cudaFuncSetAttribute(hmma_gemm<4,0,1>, cudaFuncAttributeMaxDynamicSharedMemorySize, GEMM_SMEM_T1);
    cudaFuncSetAttribute(hmma_gemm<0,2,1>, cudaFuncAttributeMaxDynamicSharedMemorySize, GEMM_SMEM_T1);
    cudaFuncSetAttribute(hmma_gemm<2,0,1>, cudaFuncAttributeMaxDynamicSharedMemorySize, GEMM_SMEM_T1);
    cudaFuncSetAttribute(hmma_gemm<1,1,2>, cudaFuncAttributeMaxDynamicSharedMemorySize, GEMM_SMEM_T2);
    cudaFuncSetAttribute(hmma_gemm<2,1,2>, cudaFuncAttributeMaxDynamicSharedMemorySize, GEMM_SMEM_T2);
    cudaFuncSetAttribute(hmma_gemm<0,0,2>, cudaFuncAttributeMaxDynamicSharedMemorySize, GEMM_SMEM_T2);
    cudaFuncSetAttribute(k_pool_f, cudaFuncAttributeMaxDynamicSharedMemorySize, POOLF_SMEM);

    __half *wgh = wh + 0*(size_t)DD_;
    __half *wih = wh + 1*(size_t)DD_;
    __half *wqh = wh + 2*(size_t)DD_;
    __half *wmh = wh + 5*(size_t)DD_;
    __half *wuh = wh + 6*(size_t)DD_;
    __half *wdh = wh + 7*(size_t)DD_;
    __half *woh = wh + 8*(size_t)DD_;

    dim3 gBig(D_ / BN_G, T_ / BM_G);          // (8, 256)
    dim3 gQkv(3 * D_ / BN_G, T_ / BM_G);      // (24, 256)
    dim3 gSm(D_ / BN_G, P_ / BM_G);           // (8, 16)

    // 0: weight split
    k_split_all<<<dim3(DD_ / 4 / 256, 9), 256>>>(w_gate, w_in, w_qkv, w_intra,
                                                 w_up, w_down, w_out, wh);
    // 1: x1 = rmsnorm(patch + pos) -> hi plane
    k_add_pos_norm_h1<<<T_, 256>>>(patch, pos, ah);
    // 2: gate = silu(x1@Wg^T) fp16
    hmma_gemm<1,2,1><<<gBig, 256, GEMM_SMEM_T1>>>(T_, D_, D_, ah, nullptr, wgh,
                                                  nullptr, nullptr, nullptr, t1h, nullptr);
    // 3: x = gate_fp16 * (x1@Wi^T)  (profiled launch)
    hmma_gemm<4,0,1><<<gBig, 256, GEMM_SMEM_T1>>>(T_, D_, D_, ah, nullptr, wih,
                                                  nullptr, t1h, p_x, nullptr, nullptr);
    // 4: conv + residual + rmsnorm (fused)
    k_conv_norm<<<P_, 1024>>>(p_x, conv_w, ah);
    // 5-7: attention block
    hmma_gemm<0,2,1><<<gQkv, 256, GEMM_SMEM_T1>>>(T_, 3 * D_, D_, ah, nullptr, wqh,
                                                  nullptr, nullptr, nullptr, qkvh, nullptr);
    k_attn<<<dim3(P_, NH_), 256>>>(qkvh, ah);
    hmma_gemm<2,0,1><<<gBig, 256, GEMM_SMEM_T1>>>(T_, D_, D_, ah, nullptr, wmh,
                                                  p_x, nullptr, p_t2, nullptr, nullptr);
    // 8: fused rmsnorm + pooling
    k_pool_f<<<P_, 256, POOLF_SMEM>>>(p_t2, w_pool, temp, p_p0);
    // 9-13: patch-level MLP + out proj + final norm (2-term tail)
    k_rmsnorm_h<<<P_, 256>>>(p_p0, s1h, s1l);
    hmma_gemm<1,1,2><<<gSm, 256, GEMM_SMEM_T2>>>(P_, D_, D_, s1h, s1l, wuh,
                                                 nullptr, nullptr, nullptr, s2h, s2l);
    hmma_gemm<2,1,2><<<gSm, 256, GEMM_SMEM_T2>>>(P_, D_, D_, s2h, s2l, wdh,
                                                 p_p0, nullptr, nullptr, s1h, s1l);
    hmma_gemm<0,0,2><<<gSm, 256, GEMM_SMEM_T2>>>(P_, D_, D_, s1h, s1l, woh,
                                                 nullptr, nullptr, p_p2, nullptr, nullptr);
    k_rmsnorm<<<P_, 256>>>(p_p2, out);
}

// round 16
// speedup vs baseline: 1.1228x; 1.1228x over previous
#include <cuda_runtime.h>
#include <cuda_fp16.h>
#include <stdint.h>
#include <math.h>

// ---------------- problem constants ----------------
#define B_    4
#define NP_   512
#define PS_   16
#define D_    1024
#define NH_   4
#define HD_   256
#define PH_   4
#define KW_   5
#define T_    (B_*NP_*PS_)        // 32768 tokens
#define P_    (B_*NP_)            // 2048 patches
#define DD_   (D_*D_)
#define EPS_  1.1920929e-7f

// ---------------- device scratch ----------------
__device__ float g_x  [(size_t)T_*D_];
__device__ float g_t2 [(size_t)T_*D_];
__device__ float g_p0 [(size_t)P_*D_];
__device__ float g_p2 [(size_t)P_*D_];

// fp16 buffers
__device__ __half g_ah  [(size_t)T_*D_];
__device__ __half g_t1h [(size_t)T_*D_];
__device__ __half g_qkvh[(size_t)T_*3*D_];
__device__ __half g_wh[(size_t)9*DD_];
__device__ __half g_s1h[(size_t)P_*D_], g_s1l[(size_t)P_*D_];
__device__ __half g_s2h[(size_t)P_*D_], g_s2l[(size_t)P_*D_];

// ---------------- helpers ----------------
__device__ __forceinline__ uint32_t smem_u32(const void* p) {
    uint32_t a;
    asm("{ .reg .u64 t; cvta.to.shared.u64 t, %1; cvt.u32.u64 %0, t; }" : "=r"(a) : "l"(p));
    return a;
}
__device__ __forceinline__ void cvt_split_h(float x0, float x1,
                                            uint32_t& hw, uint32_t& lw) {
    uint32_t h;
    asm("cvt.rn.f16x2.f32 %0, %1, %2;" : "=r"(h) : "f"(x1), "f"(x0));
    __half2 hh = *reinterpret_cast<__half2*>(&h);
    float l0 = x0 - __half2float(__low2half(hh));
    float l1 = x1 - __half2float(__high2half(hh));
    asm("cvt.rn.f16x2.f32 %0, %1, %2;" : "=r"(lw) : "f"(l1), "f"(l0));
    hw = h;
}
__device__ __forceinline__ uint32_t cvt_h2(float x0, float x1) {
    uint32_t h;
    asm("cvt.rn.f16x2.f32 %0, %1, %2;" : "=r"(h) : "f"(x1), "f"(x0));
    return h;
}

#define MMA_F16(d, a, b) \
    asm volatile("mma.sync.aligned.m16n8k16.row.col.f32.f16.f16.f32 " \
        "{%0,%1,%2,%3},{%4,%5,%6,%7},{%8,%9},{%0,%1,%2,%3};" \
        : "+f"((d)[0]), "+f"((d)[1]), "+f"((d)[2]), "+f"((d)[3]) \
        : "r"((a)[0]), "r"((a)[1]), "r"((a)[2]), "r"((a)[3]), \
          "r"((b)[0]), "r"((b)[1]))

#define LDSM_X4(r, a) \
    asm volatile("ldmatrix.sync.aligned.m8n8.x4.shared.b16 {%0,%1,%2,%3}, [%4];" \
        : "=r"((r)[0]), "=r"((r)[1]), "=r"((r)[2]), "=r"((r)[3]) : "r"(a))

#define CP16(dst, src) \
    asm volatile("cp.async.cg.shared.global [%0], [%1], 16;" :: "r"(dst), "l"(src))
#define CP_COMMIT() asm volatile("cp.async.commit_group;" ::: "memory")
#define CP_WAIT(n)  asm volatile("cp.async.wait_group %0;" :: "n"(n) : "memory")

// ================= fp16 split HMMA GEMM (R14 mainloop, no prefetch) ========
// Tile 128x128, 256 thr (8 warps = 4m x 2n, warp tile 32x64), BK=32, 2 CTAs/SM.
// TERMS=1: 5-stage ring; TERMS=2: 3-stage ring.
#define BM_G 128
#define BN_G 128
#define BK_G 32
#define PITCH 80
#define SSZ_T1 ((BM_G + BN_G) * PITCH)        // 20480
#define SSZ_T2 ((2 * BM_G + BN_G) * PITCH)    // 30720
#define GEMM_SMEM_T1 (5 * SSZ_T1)             // 102400
#define GEMM_SMEM_T2 (3 * SSZ_T2)             // 92160

// EPI: 0=v; 1=silu(v); 2=v+aux(f32); 3=silu(aux f32)*v; 4=auxh(f16)*v.
// OUTM: 0 = f32 C; 1 = fp16 hi/lo planes; 2 = fp16 single.
template <int EPI, int OUTM, int TERMS>
__global__ __launch_bounds__(256, 2)
void hmma_gemm(int M, int N, int Kd,
               const __half* __restrict__ Ahp, const __half* __restrict__ Alp,
               const __half* __restrict__ Bhp,
               const float* __restrict__ aux, const __half* __restrict__ auxh,
               float* __restrict__ C,
               __half* __restrict__ Ch, __half* __restrict__ Cl) {
    constexpr int NS   = (TERMS == 1) ? 5 : 3;
    constexpr int WCAP = NS - 2;
    constexpr uint32_t ALO_OFF = BM_G * PITCH;
    constexpr uint32_t BHI_OFF = (uint32_t)TERMS * BM_G * PITCH;
    constexpr uint32_t SSZ = (uint32_t)(TERMS * BM_G + BN_G) * PITCH;

    extern __shared__ uint8_t sm[];
    const uint32_t sb = smem_u32(sm);
    const int tid = threadIdx.x;
    const int warp = tid >> 5, lane = tid & 31;
    const int qr = lane >> 2, qc = lane & 3;
    const int wm = warp & 3, wn = warp >> 2;
    const int bx = blockIdx.x, by = blockIdx.y;

    const __half* Ahg = Ahp + (size_t)(by * BM_G) * Kd;
    const __half* Alg = (TERMS == 2) ? (Alp + (size_t)(by * BM_G) * Kd) : nullptr;
    const __half* Bhg = Bhp + (size_t)(bx * BN_G) * Kd;

    float acc[2][8][4];
#pragma unroll
    for (int i = 0; i < 2; i++)
#pragma unroll
        for (int j = 0; j < 8; j++)
#pragma unroll
            for (int r = 0; r < 4; r++) acc[i][j][r] = 0.f;

    const int trow = tid >> 2, seg = tid & 3;
    const uint32_t aAddr = (uint32_t)(wm * 32 + (lane & 15)) * PITCH + (uint32_t)(lane >> 4) * 16;
    const uint32_t bAddr = (uint32_t)(wn * 64 + (lane & 7)) * PITCH + (uint32_t)(lane >> 3) * 16;

    auto ISSUE = [&](int kt) {
        const uint32_t st = sb + (uint32_t)(kt % NS) * SSZ;
        const int kb = kt * BK_G + seg * 8;
        const uint32_t o0 = (uint32_t)trow * PITCH + (uint32_t)seg * 16;
        const uint32_t o1 = o0 + 64u * PITCH;
        CP16(st + o0, Ahg + (size_t)trow * Kd + kb);
        CP16(st + o1, Ahg + (size_t)(trow + 64) * Kd + kb);
        if (TERMS == 2) {
            CP16(st + ALO_OFF + o0, Alg + (size_t)trow * Kd + kb);
            CP16(st + ALO_OFF + o1, Alg + (size_t)(trow + 64) * Kd + kb);
        }
        CP16(st + BHI_OFF + o0, Bhg + (size_t)trow * Kd + kb);
        CP16(st + BHI_OFF + o1, Bhg + (size_t)(trow + 64) * Kd + kb);
        CP_COMMIT();
    };

    const int nk = Kd / BK_G;
#pragma unroll
    for (int s = 0; s < NS - 1; s++)
        if (s < nk) ISSUE(s);

    for (int kt = 0; kt < nk; kt++) {
        const int pend = nk - 1 - kt;
        if (pend >= WCAP) { CP_WAIT(WCAP); }
        else if (WCAP >= 3 && pend == 2) { CP_WAIT(2); }
        else if (pend == 1) { CP_WAIT(1); }
        else if (pend <= 0) { CP_WAIT(0); }
        else { CP_WAIT(1); }
        __syncthreads();
        if (kt + NS - 1 < nk) ISSUE(kt + NS - 1);

        const uint32_t st = sb + (uint32_t)(kt % NS) * SSZ;
        uint32_t bf[8][4];
#pragma unroll
        for (int nf = 0; nf < 8; nf++)
            LDSM_X4(bf[nf], st + BHI_OFF + bAddr + (uint32_t)nf * (8 * PITCH));
#pragma unroll
        for (int ks = 0; ks < 2; ks++) {
            uint32_t ah[2][4], al[2][4];
#pragma unroll
            for (int mf = 0; mf < 2; mf++) {
                const uint32_t a = st + aAddr + (uint32_t)mf * (16 * PITCH) + (uint32_t)ks * 32;
                LDSM_X4(ah[mf], a);
                if (TERMS == 2) LDSM_X4(al[mf], a + ALO_OFF);
            }
#pragma unroll
            for (int nf = 0; nf < 8; nf++) {
#pragma unroll
                for (int mf = 0; mf < 2; mf++) {
                    MMA_F16(acc[mf][nf], ah[mf], &bf[nf][2 * ks]);
                    if (TERMS == 2) MMA_F16(acc[mf][nf], al[mf], &bf[nf][2 * ks]);
                }
            }
        }
    }

    // ---- epilogue ----
    const int row0 = by * BM_G + wm * 32;
    const int col0 = bx * BN_G + wn * 64;
#pragma unroll
    for (int mf = 0; mf < 2; mf++) {
#pragma unroll
        for (int nf = 0; nf < 8; nf++) {
            const int r = row0 + mf * 16 + qr;
            const int c = col0 + nf * 8 + qc * 2;
            float v0 = acc[mf][nf][0], v1 = acc[mf][nf][1];
            float v2 = acc[mf][nf][2], v3 = acc[mf][nf][3];
            if (EPI == 1) {
                v0 = v0 / (1.f + __expf(-v0)); v1 = v1 / (1.f + __expf(-v1));
                v2 = v2 / (1.f + __expf(-v2)); v3 = v3 / (1.f + __expf(-v3));
            }
            if (EPI == 2) {
                const float* a0 = aux + (size_t)r * N + c;
                const float* a1 = aux + (size_t)(r + 8) * N + c;
                v0 += a0[0]; v1 += a0[1]; v2 += a1[0]; v3 += a1[1];
            }
            if (EPI == 3) {
                const float* a0 = aux + (size_t)r * N + c;
                const float* a1 = aux + (size_t)(r + 8) * N + c;
                float g0 = a0[0], g1 = a0[1], g2 = a1[0], g3 = a1[1];
                v0 *= g0 / (1.f + __expf(-g0)); v1 *= g1 / (1.f + __expf(-g1));
                v2 *= g2 / (1.f + __expf(-g2)); v3 *= g3 / (1.f + __expf(-g3));
            }
            if (EPI == 4) {
                __half2 a0 = *(const __half2*)(auxh + (size_t)r * N + c);
                __half2 a1 = *(const __half2*)(auxh + (size_t)(r + 8) * N + c);
                v0 *= __half2float(__low2half(a0)); v1 *= __half2float(__high2half(a0));
                v2 *= __half2float(__low2half(a1)); v3 *= __half2float(__high2half(a1));
            }
            if (OUTM == 0) {
                *(float2*)(C + (size_t)r * N + c) = make_float2(v0, v1);
                *(float2*)(C + (size_t)(r + 8) * N + c) = make_float2(v2, v3);
            } else if (OUTM == 1) {
                uint32_t hw, lw;
                cvt_split_h(v0, v1, hw, lw);
                *(uint32_t*)(Ch + (size_t)r * N + c) = hw;
                *(uint32_t*)(Cl + (size_t)r * N + c) = lw;
                cvt_split_h(v2, v3, hw, lw);
                *(uint32_t*)(Ch + (size_t)(r + 8) * N + c) = hw;
                *(uint32_t*)(Cl + (size_t)(r + 8) * N + c) = lw;
            } else {
                *(uint32_t*)(Ch + (size_t)r * N + c) = cvt_h2(v0, v1);
                *(uint32_t*)(Ch + (size_t)(r + 8) * N + c) = cvt_h2(v2, v3);
            }
        }
    }
}

// ================= aux kernels =================
__device__ __forceinline__ float warp_sum(float v) {
#pragma unroll
    for (int o = 16; o; o >>= 1) v += __shfl_down_sync(0xffffffffu, v, o);
    return v;
}
__device__ __forceinline__ float block_sum_256(float v, float* red) {
    int lane = threadIdx.x & 31, w = threadIdx.x >> 5;
    v = warp_sum(v);
    if (lane == 0) red[w] = v;
    __syncthreads();
    if (w == 0) {
        float x = (lane < 8) ? red[lane] : 0.f;
        x = warp_sum(x);
        if (lane == 0) red[0] = x;
    }
    __syncthreads();
    return red[0];
}

__global__ void k_split_all(const float* __restrict__ wg, const float* __restrict__ wi,
                            const float* __restrict__ wq, const float* __restrict__ wm,
                            const float* __restrict__ wu, const float* __restrict__ wd,
                            const float* __restrict__ wo, __half* __restrict__ wh) {
    const int y = blockIdx.y;
    const float* src;
    if      (y == 0) src = wg;
    else if (y == 1) src = wi;
    else if (y <  5) src = wq + (size_t)(y - 2) * DD_;
    else if (y == 5) src = wm;
    else if (y == 6) src = wu;
    else if (y == 7) src = wd;
    else             src = wo;
    const size_t base = (size_t)y * DD_;
    const int i = blockIdx.x * blockDim.x + threadIdx.x;
    float4 v = ((const float4*)src)[i];
    ((uint2*)(wh + base))[i] = make_uint2(cvt_h2(v.x, v.y), cvt_h2(v.z, v.w));
}

__global__ void k_add_pos_norm_h1(const float* __restrict__ x,
                                  const float* __restrict__ pos,
                                  __half* __restrict__ oh) {
    __shared__ float red[8];
    int row = blockIdx.x, t = threadIdx.x;
    float4 a = ((const float4*)(x + (size_t)row * D_))[t];
    float4 b = ((const float4*)(pos + (size_t)(row & (PS_ - 1)) * D_))[t];
    a.x += b.x; a.y += b.y; a.z += b.z; a.w += b.w;
    float tot = block_sum_256(a.x*a.x + a.y*a.y + a.z*a.z + a.w*a.w, red);
    float s = rsqrtf(tot * (1.0f / D_) + EPS_);
    ((uint2*)(oh + (size_t)row * D_))[t] =
        make_uint2(cvt_h2(a.x * s, a.y * s), cvt_h2(a.z * s, a.w * s));
}

__global__ void k_rmsnorm_h(const float* __restrict__ x,
                            __half* __restrict__ oh, __half* __restrict__ ol) {
    __shared__ float red[8];
    int row = blockIdx.x, t = threadIdx.x;
    float4 a = ((const float4*)(x + (size_t)row * D_))[t];
    float tot = block_sum_256(a.x*a.x + a.y*a.y + a.z*a.z + a.w*a.w, red);
    float s = rsqrtf(tot * (1.0f / D_) + EPS_);
    uint32_t h0, l0, h1, l1;
    cvt_split_h(a.x * s, a.y * s, h0, l0);
    cvt_split_h(a.z * s, a.w * s, h1, l1);
    ((uint2*)(oh + (size_t)row * D_))[t] = make_uint2(h0, h1);
    ((uint2*)(ol + (size_t)row * D_))[t] = make_uint2(l0, l1);
}

__global__ void k_rmsnorm(const float* __restrict__ x, float* __restrict__ out) {
    __shared__ float red[8];
    int row = blockIdx.x, t = threadIdx.x;
    float4 a = ((const float4*)(x + (size_t)row * D_))[t];
    float tot = block_sum_256(a.x*a.x + a.y*a.y + a.z*a.z + a.w*a.w, red);
    float s = rsqrtf(tot * (1.0f / D_) + EPS_);
    ((float4*)(out + (size_t)row * D_))[t] = make_float4(a.x*s, a.y*s, a.z*s, a.w*s);
}

// fused depthwise conv + residual + rmsnorm: block = patch, 1024 thr (1/channel)
__global__ __launch_bounds__(1024, 1)
void k_conv_norm(float* __restrict__ x, const float* __restrict__ w,
                 __half* __restrict__ oh) {
    __shared__ float red[PS_][33];
    __shared__ float sscale[PS_];
    const int patch = blockIdx.x, c = threadIdx.x;
    const int lane = c & 31, wid = c >> 5;

    float wk[KW_];
#pragma unroll
    for (int k = 0; k < KW_; k++) wk[k] = w[c * KW_ + k];
    const size_t base = (size_t)patch * PS_ * D_ + c;
    float v[PS_], o[PS_];
#pragma unroll
    for (int p = 0; p < PS_; p++) v[p] = x[base + (size_t)p * D_];
#pragma unroll
    for (int p = 0; p < PS_; p++) {
        float acc = v[p];
#pragma unroll
        for (int k = 0; k < KW_; k++) {
            int src = p + k - (KW_ - 1);
            if (src >= 0) acc += v[src] * wk[k];
        }
        o[p] = acc;
        x[base + (size_t)p * D_] = acc;          // residual stream (fp32)
    }
#pragma unroll
    for (int p = 0; p < PS_; p++) {
        float s = warp_sum(o[p] * o[p]);
        if (lane == 0) red[p][wid] = s;
    }
    __syncthreads();
    if (wid < PS_) {
        float s = warp_sum(red[wid][lane]);
        if (lane == 0) sscale[wid] = rsqrtf(s * (1.0f / D_) + EPS_);
    }
    __syncthreads();
#pragma unroll
    for (int p = 0; p < PS_; p++)
        oh[base + (size_t)p * D_] = __float2half(o[p] * sscale[p]);
}

// attention; fp16 qkv in, fp16 hi plane out
__global__ void k_attn(const __half* __restrict__ qkv, __half* __restrict__ oh) {
    __shared__ float bufA[PS_ * HD_];
    __shared__ float bufK[HD_ * (PS_ + 1)];
    __shared__ float S[PS_][PS_ + 1];
    int patch = blockIdx.x, h = blockIdx.y, t = threadIdx.x;

    for (int i = t; i < PS_ * HD_; i += 256) {
        int p = i >> 8, d = i & (HD_ - 1);
        size_t base = ((size_t)(patch * PS_ + p)) * (3 * D_) + (size_t)h * HD_;
        bufA[p * HD_ + d] = __half2float(qkv[base + d]);
        bufK[d * (PS_ + 1) + p] = __half2float(qkv[base + D_ + d]);
    }
    __syncthreads();
    {
        int i = t >> 4, j = t & 15;
        float acc = 0.f;
#pragma unroll 8
        for (int d = 0; d < HD_; d++)
            acc += bufA[i * HD_ + d] * bufK[d * (PS_ + 1) + j];
        S[i][j] = acc * 0.0625f;
    }
    __syncthreads();
    for (int i = t; i < PS_ * HD_; i += 256) {
        int p = i >> 8, d = i & (HD_ - 1);
        size_t base = ((size_t)(patch * PS_ + p)) * (3 * D_) + (size_t)h * HD_;
        bufA[p * HD_ + d] = __half2float(qkv[base + 2 * D_ + d]);
    }
    if (t < PS_) {
        float lv[PS_], m = -1e30f;
#pragma unroll
        for (int j = 0; j < PS_; j++) { lv[j] = S[t][j]; m = fmaxf(m, lv[j]); }
        float s = 0.f;
#pragma unroll
        for (int j = 0; j < PS_; j++) { lv[j] = __expf(lv[j] - m); s += lv[j]; }
        float inv = 1.f / s;
#pragma unroll
        for (int j = 0; j < PS_; j++) S[t][j] = lv[j] * inv;
    }
    __syncthreads();
    {
        int i = t >> 4, dc = t & 15;
        float acc[16];
#pragma unroll
        for (int r = 0; r < 16; r++) acc[r] = 0.f;
#pragma unroll
        for (int j = 0; j < PS_; j++) {
            float s = S[i][j];
#pragma unroll
            for (int r = 0; r < 16; r++)
                acc[r] += s * bufA[j * HD_ + dc * 16 + r];
        }
        size_t ob = ((size_t)(patch * PS_ + i)) * D_ + (size_t)h * HD_ + dc * 16;
        uint32_t hw[8];
#pragma unroll
        for (int p = 0; p < 8; p++) hw[p] = cvt_h2(acc[2*p], acc[2*p+1]);
        ((uint4*)(oh + ob))[0] = make_uint4(hw[0], hw[1], hw[2], hw[3]);
        ((uint4*)(oh + ob))[1] = make_uint4(hw[4], hw[5], hw[6], hw[7]);
    }
}

// fused rmsnorm + attention pooling
#define POOLF_SMEM ((PS_*D_ + PH_*D_ + PS_ + PH_*PS_ + 32) * 4)
__global__ __launch_bounds__(256, 2)
void k_pool_f(const float* __restrict__ x4, const float* __restrict__ wpool,
              const float* __restrict__ temp, float* __restrict__ out) {
    extern __shared__ float psm[];
    float* sx   = psm;
    float* swp  = sx + PS_ * D_;
    float* srow = swp + PH_ * D_;
    float* slog = srow + PS_;
    int patch = blockIdx.x, t = threadIdx.x;
    int w = t >> 5, lane = t & 31;

#pragma unroll
    for (int rr = 0; rr < 2; rr++) {
        int p = w * 2 + rr;
        const float4* src = (const float4*)(x4 + ((size_t)patch * PS_ + p) * D_);
        float ss = 0.f;
#pragma unroll
        for (int i = 0; i < 8; i++) {
            float4 v = src[lane + 32 * i];
            ((float4*)(sx + p * D_))[lane + 32 * i] = v;
            ss += v.x*v.x + v.y*v.y + v.z*v.z + v.w*v.w;
        }
        ss = warp_sum(ss);
        if (lane == 0) srow[p] = rsqrtf(ss * (1.0f / D_) + EPS_);
    }
    for (int i = t; i < PH_ * D_; i += 256) swp[i] = wpool[i];
    __syncthreads();

    for (int p = w; p < PS_; p += 8) {
        const float* xr = sx + p * D_;
        float a0 = 0, a1 = 0, a2 = 0, a3 = 0;
        for (int d = lane; d < D_; d += 32) {
            float xv = xr[d];
            a0 += xv * swp[d];
            a1 += xv * swp[D_ + d];
            a2 += xv * swp[2 * D_ + d];
            a3 += xv * swp[3 * D_ + d];
        }
        a0 = warp_sum(a0); a1 = warp_sum(a1); a2 = warp_sum(a2); a3 = warp_sum(a3);
        if (lane == 0) {
            float s = srow[p];
            slog[0 * PS_ + p] = a0 * s; slog[1 * PS_ + p] = a1 * s;
            slog[2 * PS_ + p] = a2 * s; slog[3 * PS_ + p] = a3 * s;
        }
    }
    __syncthreads();
    if (t < PH_) {
        float inv = 1.f / fmaxf(temp[0], 0.01f);
        float lv[PS_], m = -1e30f;
#pragma unroll
        for (int p = 0; p < PS_; p++) { lv[p] = slog[t * PS_ + p] * inv; m = fmaxf(m, lv[p]); }
        float s = 0.f;
#pragma unroll
        for (int p = 0; p < PS_; p++) { lv[p] = __expf(lv[p] - m); s += lv[p]; }
        float is = 1.f / s;
#pragma unroll
        for (int p = 0; p < PS_; p++) slog[t * PS_ + p] = lv[p] * is;
    }
    __syncthreads();
    int dd = t * 4;
    int h = dd >> 8;
    float4 acc = make_float4(0, 0, 0, 0);
#pragma unroll
    for (int p = 0; p < PS_; p++) {
        float wg = slog[h * PS_ + p] * srow[p];
        float4 xv = *(const float4*)(sx + p * D_ + dd);
        acc.x += wg * xv.x; acc.y += wg * xv.y; acc.z += wg * xv.z; acc.w += wg * xv.w;
    }
    *(float4*)(out + (size_t)patch * D_ + dd) = acc;
}

// ================= launch =================
extern "C" void kernel_launch(void* const* d_in, const int* in_sizes, int n_in,
                              void* d_out, int out_size) {
    const float* patch   = (const float*)d_in[0];
    const float* pos     = (const float*)d_in[1];
    const float* w_gate  = (const float*)d_in[2];
    const float* w_in    = (const float*)d_in[3];
    const float* conv_w  = (const float*)d_in[4];
    const float* w_qkv   = (const float*)d_in[5];
    const float* w_intra = (const float*)d_in[6];
    const float* w_pool  = (const float*)d_in[7];
    const float* temp    = (const float*)d_in[8];
    const float* w_up    = (const float*)d_in[9];
    const float* w_down  = (const float*)d_in[10];
    const float* w_out   = (const float*)d_in[11];
    float* out = (float*)d_out;

    float *p_x, *p_t2, *p_p0, *p_p2;
    cudaGetSymbolAddress((void**)&p_x,   g_x);
    cudaGetSymbolAddress((void**)&p_t2,  g_t2);
    cudaGetSymbolAddress((void**)&p_p0,  g_p0);
    cudaGetSymbolAddress((void**)&p_p2,  g_p2);

    __half *ah, *t1h, *qkvh, *wh, *s1h, *s1l, *s2h, *s2l;
    cudaGetSymbolAddress((void**)&ah,   g_ah);
    cudaGetSymbolAddress((void**)&t1h,  g_t1h);
    cudaGetSymbolAddress((void**)&qkvh, g_qkvh);
    cudaGetSymbolAddress((void**)&wh,   g_wh);
    cudaGetSymbolAddress((void**)&s1h, g_s1h); cudaGetSymbolAddress((void**)&s1l, g_s1l);
    cudaGetSymbolAddress((void**)&s2h, g_s2h); cudaGetSymbolAddress((void**)&s2l, g_s2l);

    cudaFuncSetAttribute(hmma_gemm<1,2,1>, cudaFuncAttributeMaxDynamicSharedMemorySize, GEMM_SMEM_T1);
    cudaFuncSetAttribute(hmma_gemm<4,0,1>, cudaFuncAttributeMaxDynamicSharedMemorySize, GEMM_SMEM_T1);
    cudaFuncSetAttribute(hmma_gemm<0,2,1>, cudaFuncAttributeMaxDynamicSharedMemorySize, GEMM_SMEM_T1);
    cudaFuncSetAttribute(hmma_gemm<2,0,1>, cudaFuncAttributeMaxDynamicSharedMemorySize, GEMM_SMEM_T1);
    cudaFuncSetAttribute(hmma_gemm<1,1,2>, cudaFuncAttributeMaxDynamicSharedMemorySize, GEMM_SMEM_T2);
    cudaFuncSetAttribute(hmma_gemm<2,1,2>, cudaFuncAttributeMaxDynamicSharedMemorySize, GEMM_SMEM_T2);
    cudaFuncSetAttribute(hmma_gemm<0,0,2>, cudaFuncAttributeMaxDynamicSharedMemorySize, GEMM_SMEM_T2);
    cudaFuncSetAttribute(k_pool_f, cudaFuncAttributeMaxDynamicSharedMemorySize, POOLF_SMEM);

    __half *wgh = wh + 0*(size_t)DD_;
    __half *wih = wh + 1*(size_t)DD_;
    __half *wqh = wh + 2*(size_t)DD_;
    __half *wmh = wh + 5*(size_t)DD_;
    __half *wuh = wh + 6*(size_t)DD_;
    __half *wdh = wh + 7*(size_t)DD_;
    __half *woh = wh + 8*(size_t)DD_;

    dim3 gBig(D_ / BN_G, T_ / BM_G);          // (8, 256)
    dim3 gQkv(3 * D_ / BN_G, T_ / BM_G);      // (24, 256)
    dim3 gSm(D_ / BN_G, P_ / BM_G);           // (8, 16)

    // 0: weight split
    k_split_all<<<dim3(DD_ / 4 / 256, 9), 256>>>(w_gate, w_in, w_qkv, w_intra,
                                                 w_up, w_down, w_out, wh);
    // 1: x1 = rmsnorm(patch + pos) -> hi plane
    k_add_pos_norm_h1<<<T_, 256>>>(patch, pos, ah);
    // 2: gate = silu(x1@Wg^T) fp16
    hmma_gemm<1,2,1><<<gBig, 256, GEMM_SMEM_T1>>>(T_, D_, D_, ah, nullptr, wgh,
                                                  nullptr, nullptr, nullptr, t1h, nullptr);
    // 3: x = gate_fp16 * (x1@Wi^T)  (profiled launch)
    hmma_gemm<4,0,1><<<gBig, 256, GEMM_SMEM_T1>>>(T_, D_, D_, ah, nullptr, wih,
                                                  nullptr, t1h, p_x, nullptr, nullptr);
    // 4: conv + residual + rmsnorm (fused)
    k_conv_norm<<<P_, 1024>>>(p_x, conv_w, ah);
    // 5-7: attention block
    hmma_gemm<0,2,1><<<gQkv, 256, GEMM_SMEM_T1>>>(T_, 3 * D_, D_, ah, nullptr, wqh,
                                                  nullptr, nullptr, nullptr, qkvh, nullptr);
    k_attn<<<dim3(P_, NH_), 256>>>(qkvh, ah);
    hmma_gemm<2,0,1><<<gBig, 256, GEMM_SMEM_T1>>>(T_, D_, D_, ah, nullptr, wmh,
                                                  p_x, nullptr, p_t2, nullptr, nullptr);
    // 8: fused rmsnorm + pooling
    k_pool_f<<<P_, 256, POOLF_SMEM>>>(p_t2, w_pool, temp, p_p0);
    // 9-13: patch-level MLP + out proj + final norm (2-term tail)
    k_rmsnorm_h<<<P_, 256>>>(p_p0, s1h, s1l);
    hmma_gemm<1,1,2><<<gSm, 256, GEMM_SMEM_T2>>>(P_, D_, D_, s1h, s1l, wuh,
                                                 nullptr, nullptr, nullptr, s2h, s2l);
    hmma_gemm<2,1,2><<<gSm, 256, GEMM_SMEM_T2>>>(P_, D_, D_, s2h, s2l, wdh,
                                                 p_p0, nullptr, nullptr, s1h, s1l);
    hmma_gemm<0,0,2><<<gSm, 256, GEMM_SMEM_T2>>>(P_, D_, D_, s1h, s1l, woh,
                                                 nullptr, nullptr, p_p2, nullptr, nullptr);
    k_rmsnorm<<<P_, 256>>>(p_p2, out);
}

// round 17
// speedup vs baseline: 1.1718x; 1.0437x over previous
#include <cuda_runtime.h>
#include <cuda_fp16.h>
#include <stdint.h>
#include <math.h>

// ---------------- problem constants ----------------
#define B_    4
#define NP_   512
#define PS_   16
#define D_    1024
#define NH_   4
#define HD_   256
#define PH_   4
#define KW_   5
#define T_    (B_*NP_*PS_)        // 32768 tokens
#define P_    (B_*NP_)            // 2048 patches
#define DD_   (D_*D_)
#define EPS_  1.1920929e-7f

// ---------------- device scratch ----------------
__device__ float g_x  [(size_t)T_*D_];
__device__ float g_t2 [(size_t)T_*D_];
__device__ float g_p0 [(size_t)P_*D_];
__device__ float g_p2 [(size_t)P_*D_];

// fp16 buffers
__device__ __half g_ah  [(size_t)T_*D_];
__device__ __half g_qkvh[(size_t)T_*3*D_];
__device__ __half g_wh[(size_t)9*DD_];
__device__ __half g_s1h[(size_t)P_*D_];
__device__ __half g_s2h[(size_t)P_*D_];

// ---------------- helpers ----------------
__device__ __forceinline__ uint32_t smem_u32(const void* p) {
    uint32_t a;
    asm("{ .reg .u64 t; cvta.to.shared.u64 t, %1; cvt.u32.u64 %0, t; }" : "=r"(a) : "l"(p));
    return a;
}
__device__ __forceinline__ uint32_t cvt_h2(float x0, float x1) {
    uint32_t h;
    asm("cvt.rn.f16x2.f32 %0, %1, %2;" : "=r"(h) : "f"(x1), "f"(x0));
    return h;
}

#define MMA_F16(d, a, b) \
    asm volatile("mma.sync.aligned.m16n8k16.row.col.f32.f16.f16.f32 " \
        "{%0,%1,%2,%3},{%4,%5,%6,%7},{%8,%9},{%0,%1,%2,%3};" \
        : "+f"((d)[0]), "+f"((d)[1]), "+f"((d)[2]), "+f"((d)[3]) \
        : "r"((a)[0]), "r"((a)[1]), "r"((a)[2]), "r"((a)[3]), \
          "r"((b)[0]), "r"((b)[1]))

#define LDSM_X4(r, a) \
    asm volatile("ldmatrix.sync.aligned.m8n8.x4.shared.b16 {%0,%1,%2,%3}, [%4];" \
        : "=r"((r)[0]), "=r"((r)[1]), "=r"((r)[2]), "=r"((r)[3]) : "r"(a))

#define CP16(dst, src) \
    asm volatile("cp.async.cg.shared.global [%0], [%1], 16;" :: "r"(dst), "l"(src))
#define CP_COMMIT() asm volatile("cp.async.commit_group;" ::: "memory")
#define CP_WAIT(n)  asm volatile("cp.async.wait_group %0;" :: "n"(n) : "memory")

// ================= GEMM tiling constants =================
#define BM_G 128
#define BN_G 128
#define BK_G 32
#define PITCH 80
#define SSZ_T1 ((BM_G + BN_G) * PITCH)        // 20480
#define GEMM_SMEM_T1 (5 * SSZ_T1)             // 102400
#define NS_T1 5
#define WCAP_T1 (NS_T1 - 2)

// ================= single-term fp16 HMMA GEMM (proven R14/R16 core) =========
// EPI: 0=v; 1=silu(v); 2=v+aux(f32).  OUTM: 0 = f32 C; 2 = fp16 single (Ch).
template <int EPI, int OUTM>
__global__ __launch_bounds__(256, 2)
void hmma_gemm(int M, int N, int Kd,
               const __half* __restrict__ Ahp, const __half* __restrict__ Bhp,
               const float* __restrict__ aux,
               float* __restrict__ C, __half* __restrict__ Ch) {
    constexpr uint32_t BHI_OFF = (uint32_t)BM_G * PITCH;
    constexpr uint32_t SSZ = SSZ_T1;

    extern __shared__ uint8_t sm[];
    const uint32_t sb = smem_u32(sm);
    const int tid = threadIdx.x;
    const int warp = tid >> 5, lane = tid & 31;
    const int qr = lane >> 2, qc = lane & 3;
    const int wm = warp & 3, wn = warp >> 2;
    const int bx = blockIdx.x, by = blockIdx.y;

    const __half* Ahg = Ahp + (size_t)(by * BM_G) * Kd;
    const __half* Bhg = Bhp + (size_t)(bx * BN_G) * Kd;

    float acc[2][8][4];
#pragma unroll
    for (int i = 0; i < 2; i++)
#pragma unroll
        for (int j = 0; j < 8; j++)
#pragma unroll
            for (int r = 0; r < 4; r++) acc[i][j][r] = 0.f;

    const int trow = tid >> 2, seg = tid & 3;
    const uint32_t aAddr = (uint32_t)(wm * 32 + (lane & 15)) * PITCH + (uint32_t)(lane >> 4) * 16;
    const uint32_t bAddr = (uint32_t)(wn * 64 + (lane & 7)) * PITCH + (uint32_t)(lane >> 3) * 16;

    auto ISSUE = [&](int kt) {
        const uint32_t st = sb + (uint32_t)(kt % NS_T1) * SSZ;
        const int kb = kt * BK_G + seg * 8;
        const uint32_t o0 = (uint32_t)trow * PITCH + (uint32_t)seg * 16;
        const uint32_t o1 = o0 + 64u * PITCH;
        CP16(st + o0, Ahg + (size_t)trow * Kd + kb);
        CP16(st + o1, Ahg + (size_t)(trow + 64) * Kd + kb);
        CP16(st + BHI_OFF + o0, Bhg + (size_t)trow * Kd + kb);
        CP16(st + BHI_OFF + o1, Bhg + (size_t)(trow + 64) * Kd + kb);
        CP_COMMIT();
    };

    const int nk = Kd / BK_G;
#pragma unroll
    for (int s = 0; s < NS_T1 - 1; s++)
        if (s < nk) ISSUE(s);

    for (int kt = 0; kt < nk; kt++) {
        const int pend = nk - 1 - kt;
        if (pend >= WCAP_T1) { CP_WAIT(WCAP_T1); }
        else if (pend == 2) { CP_WAIT(2); }
        else if (pend == 1) { CP_WAIT(1); }
        else { CP_WAIT(0); }
        __syncthreads();
        if (kt + NS_T1 - 1 < nk) ISSUE(kt + NS_T1 - 1);

        const uint32_t st = sb + (uint32_t)(kt % NS_T1) * SSZ;
        uint32_t bf[8][4];
#pragma unroll
        for (int nf = 0; nf < 8; nf++)
            LDSM_X4(bf[nf], st + BHI_OFF + bAddr + (uint32_t)nf * (8 * PITCH));
#pragma unroll
        for (int ks = 0; ks < 2; ks++) {
            uint32_t ah[2][4];
#pragma unroll
            for (int mf = 0; mf < 2; mf++) {
                const uint32_t a = st + aAddr + (uint32_t)mf * (16 * PITCH) + (uint32_t)ks * 32;
                LDSM_X4(ah[mf], a);
            }
#pragma unroll
            for (int nf = 0; nf < 8; nf++)
#pragma unroll
                for (int mf = 0; mf < 2; mf++)
                    MMA_F16(acc[mf][nf], ah[mf], &bf[nf][2 * ks]);
        }
    }

    const int row0 = by * BM_G + wm * 32;
    const int col0 = bx * BN_G + wn * 64;
#pragma unroll
    for (int mf = 0; mf < 2; mf++) {
#pragma unroll
        for (int nf = 0; nf < 8; nf++) {
            const int r = row0 + mf * 16 + qr;
            const int c = col0 + nf * 8 + qc * 2;
            float v0 = acc[mf][nf][0], v1 = acc[mf][nf][1];
            float v2 = acc[mf][nf][2], v3 = acc[mf][nf][3];
            if (EPI == 1) {
                v0 = v0 / (1.f + __expf(-v0)); v1 = v1 / (1.f + __expf(-v1));
                v2 = v2 / (1.f + __expf(-v2)); v3 = v3 / (1.f + __expf(-v3));
            }
            if (EPI == 2) {
                const float* a0 = aux + (size_t)r * N + c;
                const float* a1 = aux + (size_t)(r + 8) * N + c;
                v0 += a0[0]; v1 += a0[1]; v2 += a1[0]; v3 += a1[1];
            }
            if (OUTM == 0) {
                *(float2*)(C + (size_t)r * N + c) = make_float2(v0, v1);
                *(float2*)(C + (size_t)(r + 8) * N + c) = make_float2(v2, v3);
            } else {
                *(uint32_t*)(Ch + (size_t)r * N + c) = cvt_h2(v0, v1);
                *(uint32_t*)(Ch + (size_t)(r + 8) * N + c) = cvt_h2(v2, v3);
            }
        }
    }
}

// ================= fused gate+in GEMM: x = silu(A@Wg^T) * (A@Wi^T) ==========
// Same core; B stage = 64 rows Wg + 64 rows Wi (same columns). Warp tile 32x32
// per output; both accumulators in-register; epilogue silu-mul -> fp32 C.
__global__ __launch_bounds__(256, 2)
void k_gatein(int N, int Kd,
              const __half* __restrict__ Ahp,
              const __half* __restrict__ Wg, const __half* __restrict__ Wi,
              float* __restrict__ C) {
    constexpr uint32_t BHI_OFF = (uint32_t)BM_G * PITCH;
    constexpr uint32_t SSZ = SSZ_T1;

    extern __shared__ uint8_t sm[];
    const uint32_t sb = smem_u32(sm);
    const int tid = threadIdx.x;
    const int warp = tid >> 5, lane = tid & 31;
    const int qr = lane >> 2, qc = lane & 3;
    const int wm = warp & 3, wn = warp >> 2;       // 4m x 2n, warp covers 32 cols
    const int bx = blockIdx.x, by = blockIdx.y;    // bx over 64-col tiles

    const __half* Ahg = Ahp + (size_t)(by * BM_G) * Kd;
    const __half* Wgg = Wg + (size_t)(bx * 64) * Kd;
    const __half* Wig = Wi + (size_t)(bx * 64) * Kd;

    float accg[2][4][4], acci[2][4][4];
#pragma unroll
    for (int i = 0; i < 2; i++)
#pragma unroll
        for (int j = 0; j < 4; j++)
#pragma unroll
            for (int r = 0; r < 4; r++) { accg[i][j][r] = 0.f; acci[i][j][r] = 0.f; }

    const int trow = tid >> 2, seg = tid & 3;
    const uint32_t aAddr = (uint32_t)(wm * 32 + (lane & 15)) * PITCH + (uint32_t)(lane >> 4) * 16;
    const uint32_t bAddr = (uint32_t)(wn * 32 + (lane & 7)) * PITCH + (uint32_t)(lane >> 3) * 16;

    auto ISSUE = [&](int kt) {
        const uint32_t st = sb + (uint32_t)(kt % NS_T1) * SSZ;
        const int kb = kt * BK_G + seg * 8;
        const uint32_t o0 = (uint32_t)trow * PITCH + (uint32_t)seg * 16;
        const uint32_t o1 = o0 + 64u * PITCH;
        CP16(st + o0, Ahg + (size_t)trow * Kd + kb);
        CP16(st + o1, Ahg + (size_t)(trow + 64) * Kd + kb);
        CP16(st + BHI_OFF + o0, Wgg + (size_t)trow * Kd + kb);   // gate rows 0..63
        CP16(st + BHI_OFF + o1, Wig + (size_t)trow * Kd + kb);   // in   rows 64..127
        CP_COMMIT();
    };

    const int nk = Kd / BK_G;
#pragma unroll
    for (int s = 0; s < NS_T1 - 1; s++)
        if (s < nk) ISSUE(s);

    for (int kt = 0; kt < nk; kt++) {
        const int pend = nk - 1 - kt;
        if (pend >= WCAP_T1) { CP_WAIT(WCAP_T1); }
        else if (pend == 2) { CP_WAIT(2); }
        else if (pend == 1) { CP_WAIT(1); }
        else { CP_WAIT(0); }
        __syncthreads();
        if (kt + NS_T1 - 1 < nk) ISSUE(kt + NS_T1 - 1);

        const uint32_t st = sb + (uint32_t)(kt % NS_T1) * SSZ;
        uint32_t bg[4][4], bi[4][4];
#pragma unroll
        for (int nf = 0; nf < 4; nf++) {
            const uint32_t a = st + BHI_OFF + bAddr + (uint32_t)nf * (8 * PITCH);
            LDSM_X4(bg[nf], a);
            LDSM_X4(bi[nf], a + 64u * PITCH);
        }
#pragma unroll
        for (int ks = 0; ks < 2; ks++) {
            uint32_t ah[2][4];
#pragma unroll
            for (int mf = 0; mf < 2; mf++) {
                const uint32_t a = st + aAddr + (uint32_t)mf * (16 * PITCH) + (uint32_t)ks * 32;
                LDSM_X4(ah[mf], a);
            }
#pragma unroll
            for (int nf = 0; nf < 4; nf++)
#pragma unroll
                for (int mf = 0; mf < 2; mf++) {
                    MMA_F16(accg[mf][nf], ah[mf], &bg[nf][2 * ks]);
                    MMA_F16(acci[mf][nf], ah[mf], &bi[nf][2 * ks]);
                }
        }
    }

    const int row0 = by * BM_G + wm * 32;
    const int col0 = bx * 64 + wn * 32;
#pragma unroll
    for (int mf = 0; mf < 2; mf++) {
#pragma unroll
        for (int nf = 0; nf < 4; nf++) {
            const int r = row0 + mf * 16 + qr;
            const int c = col0 + nf * 8 + qc * 2;
            float g0 = accg[mf][nf][0], g1 = accg[mf][nf][1];
            float g2 = accg[mf][nf][2], g3 = accg[mf][nf][3];
            float i0 = acci[mf][nf][0], i1 = acci[mf][nf][1];
            float i2 = acci[mf][nf][2], i3 = acci[mf][nf][3];
            float v0 = g0 / (1.f + __expf(-g0)) * i0;
            float v1 = g1 / (1.f + __expf(-g1)) * i1;
            float v2 = g2 / (1.f + __expf(-g2)) * i2;
            float v3 = g3 / (1.f + __expf(-g3)) * i3;
            *(float2*)(C + (size_t)r * N + c) = make_float2(v0, v1);
            *(float2*)(C + (size_t)(r + 8) * N + c) = make_float2(v2, v3);
        }
    }
}

// ================= aux kernels =================
__device__ __forceinline__ float warp_sum(float v) {
#pragma unroll
    for (int o = 16; o; o >>= 1) v += __shfl_down_sync(0xffffffffu, v, o);
    return v;
}
__device__ __forceinline__ float block_sum_256(float v, float* red) {
    int lane = threadIdx.x & 31, w = threadIdx.x >> 5;
    v = warp_sum(v);
    if (lane == 0) red[w] = v;
    __syncthreads();
    if (w == 0) {
        float x = (lane < 8) ? red[lane] : 0.f;
        x = warp_sum(x);
        if (lane == 0) red[0] = x;
    }
    __syncthreads();
    return red[0];
}

__global__ void k_split_all(const float* __restrict__ wg, const float* __restrict__ wi,
                            const float* __restrict__ wq, const float* __restrict__ wm,
                            const float* __restrict__ wu, const float* __restrict__ wd,
                            const float* __restrict__ wo, __half* __restrict__ wh) {
    const int y = blockIdx.y;
    const float* src;
    if      (y == 0) src = wg;
    else if (y == 1) src = wi;
    else if (y <  5) src = wq + (size_t)(y - 2) * DD_;
    else if (y == 5) src = wm;
    else if (y == 6) src = wu;
    else if (y == 7) src = wd;
    else             src = wo;
    const size_t base = (size_t)y * DD_;
    const int i = blockIdx.x * blockDim.x + threadIdx.x;
    float4 v = ((const float4*)src)[i];
    ((uint2*)(wh + base))[i] = make_uint2(cvt_h2(v.x, v.y), cvt_h2(v.z, v.w));
}

__global__ void k_add_pos_norm_h1(const float* __restrict__ x,
                                  const float* __restrict__ pos,
                                  __half* __restrict__ oh) {
    __shared__ float red[8];
    int row = blockIdx.x, t = threadIdx.x;
    float4 a = ((const float4*)(x + (size_t)row * D_))[t];
    float4 b = ((const float4*)(pos + (size_t)(row & (PS_ - 1)) * D_))[t];
    a.x += b.x; a.y += b.y; a.z += b.z; a.w += b.w;
    float tot = block_sum_256(a.x*a.x + a.y*a.y + a.z*a.z + a.w*a.w, red);
    float s = rsqrtf(tot * (1.0f / D_) + EPS_);
    ((uint2*)(oh + (size_t)row * D_))[t] =
        make_uint2(cvt_h2(a.x * s, a.y * s), cvt_h2(a.z * s, a.w * s));
}

__global__ void k_rmsnorm_h1(const float* __restrict__ x, __half* __restrict__ oh) {
    __shared__ float red[8];
    int row = blockIdx.x, t = threadIdx.x;
    float4 a = ((const float4*)(x + (size_t)row * D_))[t];
    float tot = block_sum_256(a.x*a.x + a.y*a.y + a.z*a.z + a.w*a.w, red);
    float s = rsqrtf(tot * (1.0f / D_) + EPS_);
    ((uint2*)(oh + (size_t)row * D_))[t] =
        make_uint2(cvt_h2(a.x * s, a.y * s), cvt_h2(a.z * s, a.w * s));
}

__global__ void k_rmsnorm(const float* __restrict__ x, float* __restrict__ out) {
    __shared__ float red[8];
    int row = blockIdx.x, t = threadIdx.x;
    float4 a = ((const float4*)(x + (size_t)row * D_))[t];
    float tot = block_sum_256(a.x*a.x + a.y*a.y + a.z*a.z + a.w*a.w, red);
    float s = rsqrtf(tot * (1.0f / D_) + EPS_);
    ((float4*)(out + (size_t)row * D_))[t] = make_float4(a.x*s, a.y*s, a.z*s, a.w*s);
}

// fused depthwise conv + residual + rmsnorm
__global__ __launch_bounds__(1024, 1)
void k_conv_norm(float* __restrict__ x, const float* __restrict__ w,
                 __half* __restrict__ oh) {
    __shared__ float red[PS_][33];
    __shared__ float sscale[PS_];
    const int patch = blockIdx.x, c = threadIdx.x;
    const int lane = c & 31, wid = c >> 5;

    float wk[KW_];
#pragma unroll
    for (int k = 0; k < KW_; k++) wk[k] = w[c * KW_ + k];
    const size_t base = (size_t)patch * PS_ * D_ + c;
    float v[PS_], o[PS_];
#pragma unroll
    for (int p = 0; p < PS_; p++) v[p] = x[base + (size_t)p * D_];
#pragma unroll
    for (int p = 0; p < PS_; p++) {
        float acc = v[p];
#pragma unroll
        for (int k = 0; k < KW_; k++) {
            int src = p + k - (KW_ - 1);
            if (src >= 0) acc += v[src] * wk[k];
        }
        o[p] = acc;
        x[base + (size_t)p * D_] = acc;
    }
#pragma unroll
    for (int p = 0; p < PS_; p++) {
        float s = warp_sum(o[p] * o[p]);
        if (lane == 0) red[p][wid] = s;
    }
    __syncthreads();
    if (wid < PS_) {
        float s = warp_sum(red[wid][lane]);
        if (lane == 0) sscale[wid] = rsqrtf(s * (1.0f / D_) + EPS_);
    }
    __syncthreads();
#pragma unroll
    for (int p = 0; p < PS_; p++)
        oh[base + (size_t)p * D_] = __float2half(o[p] * sscale[p]);
}

// attention; fp16 qkv in, fp16 hi plane out
__global__ void k_attn(const __half* __restrict__ qkv, __half* __restrict__ oh) {
    __shared__ float bufA[PS_ * HD_];
    __shared__ float bufK[HD_ * (PS_ + 1)];
    __shared__ float S[PS_][PS_ + 1];
    int patch = blockIdx.x, h = blockIdx.y, t = threadIdx.x;

    for (int i = t; i < PS_ * HD_; i += 256) {
        int p = i >> 8, d = i & (HD_ - 1);
        size_t base = ((size_t)(patch * PS_ + p)) * (3 * D_) + (size_t)h * HD_;
        bufA[p * HD_ + d] = __half2float(qkv[base + d]);
        bufK[d * (PS_ + 1) + p] = __half2float(qkv[base + D_ + d]);
    }
    __syncthreads();
    {
        int i = t >> 4, j = t & 15;
        float acc = 0.f;
#pragma unroll 8
        for (int d = 0; d < HD_; d++)
            acc += bufA[i * HD_ + d] * bufK[d * (PS_ + 1) + j];
        S[i][j] = acc * 0.0625f;
    }
    __syncthreads();
    for (int i = t; i < PS_ * HD_; i += 256) {
        int p = i >> 8, d = i & (HD_ - 1);
        size_t base = ((size_t)(patch * PS_ + p)) * (3 * D_) + (size_t)h * HD_;
        bufA[p * HD_ + d] = __half2float(qkv[base + 2 * D_ + d]);
    }
    if (t < PS_) {
        float lv[PS_], m = -1e30f;
#pragma unroll
        for (int j = 0; j < PS_; j++) { lv[j] = S[t][j]; m = fmaxf(m, lv[j]); }
        float s = 0.f;
#pragma unroll
        for (int j = 0; j < PS_; j++) { lv[j] = __expf(lv[j] - m); s += lv[j]; }
        float inv = 1.f / s;
#pragma unroll
        for (int j = 0; j < PS_; j++) S[t][j] = lv[j] * inv;
    }
    __syncthreads();
    {
        int i = t >> 4, dc = t & 15;
        float acc[16];
#pragma unroll
        for (int r = 0; r < 16; r++) acc[r] = 0.f;
#pragma unroll
        for (int j = 0; j < PS_; j++) {
            float s = S[i][j];
#pragma unroll
            for (int r = 0; r < 16; r++)
                acc[r] += s * bufA[j * HD_ + dc * 16 + r];
        }
        size_t ob = ((size_t)(patch * PS_ + i)) * D_ + (size_t)h * HD_ + dc * 16;
        uint32_t hw[8];
#pragma unroll
        for (int p = 0; p < 8; p++) hw[p] = cvt_h2(acc[2*p], acc[2*p+1]);
        ((uint4*)(oh + ob))[0] = make_uint4(hw[0], hw[1], hw[2], hw[3]);
        ((uint4*)(oh + ob))[1] = make_uint4(hw[4], hw[5], hw[6], hw[7]);
    }
}

// fused rmsnorm + attention pooling
#define POOLF_SMEM ((PS_*D_ + PH_*D_ + PS_ + PH_*PS_ + 32) * 4)
__global__ __launch_bounds__(256, 2)
void k_pool_f(const float* __restrict__ x4, const float* __restrict__ wpool,
              const float* __restrict__ temp, float* __restrict__ out) {
    extern __shared__ float psm[];
    float* sx   = psm;
    float* swp  = sx + PS_ * D_;
    float* srow = swp + PH_ * D_;
    float* slog = srow + PS_;
    int patch = blockIdx.x, t = threadIdx.x;
    int w = t >> 5, lane = t & 31;

#pragma unroll
    for (int rr = 0; rr < 2; rr++) {
        int p = w * 2 + rr;
        const float4* src = (const float4*)(x4 + ((size_t)patch * PS_ + p) * D_);
        float ss = 0.f;
#pragma unroll
        for (int i = 0; i < 8; i++) {
            float4 v = src[lane + 32 * i];
            ((float4*)(sx + p * D_))[lane + 32 * i] = v;
            ss += v.x*v.x + v.y*v.y + v.z*v.z + v.w*v.w;
        }
        ss = warp_sum(ss);
        if (lane == 0) srow[p] = rsqrtf(ss * (1.0f / D_) + EPS_);
    }
    for (int i = t; i < PH_ * D_; i += 256) swp[i] = wpool[i];
    __syncthreads();

    for (int p = w; p < PS_; p += 8) {
        const float* xr = sx + p * D_;
        float a0 = 0, a1 = 0, a2 = 0, a3 = 0;
        for (int d = lane; d < D_; d += 32) {
            float xv = xr[d];
            a0 += xv * swp[d];
            a1 += xv * swp[D_ + d];
            a2 += xv * swp[2 * D_ + d];
            a3 += xv * swp[3 * D_ + d];
        }
        a0 = warp_sum(a0); a1 = warp_sum(a1); a2 = warp_sum(a2); a3 = warp_sum(a3);
        if (lane == 0) {
            float s = srow[p];
            slog[0 * PS_ + p] = a0 * s; slog[1 * PS_ + p] = a1 * s;
            slog[2 * PS_ + p] = a2 * s; slog[3 * PS_ + p] = a3 * s;
        }
    }
    __syncthreads();
    if (t < PH_) {
        float inv = 1.f / fmaxf(temp[0], 0.01f);
        float lv[PS_], m = -1e30f;
#pragma unroll
        for (int p = 0; p < PS_; p++) { lv[p] = slog[t * PS_ + p] * inv; m = fmaxf(m, lv[p]); }
        float s = 0.f;
#pragma unroll
        for (int p = 0; p < PS_; p++) { lv[p] = __expf(lv[p] - m); s += lv[p]; }
        float is = 1.f / s;
#pragma unroll
        for (int p = 0; p < PS_; p++) slog[t * PS_ + p] = lv[p] * is;
    }
    __syncthreads();
    int dd = t * 4;
    int h = dd >> 8;
    float4 acc = make_float4(0, 0, 0, 0);
#pragma unroll
    for (int p = 0; p < PS_; p++) {
        float wg = slog[h * PS_ + p] * srow[p];
        float4 xv = *(const float4*)(sx + p * D_ + dd);
        acc.x += wg * xv.x; acc.y += wg * xv.y; acc.z += wg * xv.z; acc.w += wg * xv.w;
    }
    *(float4*)(out + (size_t)patch * D_ + dd) = acc;
}

// ================= launch =================
extern "C" void kernel_launch(void* const* d_in, const int* in_sizes, int n_in,
                              void* d_out, int out_size) {
    const float* patch   = (const float*)d_in[0];
    const float* pos     = (const float*)d_in[1];
    const float* w_gate  = (const float*)d_in[2];
    const float* w_in    = (const float*)d_in[3];
    const float* conv_w  = (const float*)d_in[4];
    const float* w_qkv   = (const float*)d_in[5];
    const float* w_intra = (const float*)d_in[6];
    const float* w_pool  = (const float*)d_in[7];
    const float* temp    = (const float*)d_in[8];
    const float* w_up    = (const float*)d_in[9];
    const float* w_down  = (const float*)d_in[10];
    const float* w_out   = (const float*)d_in[11];
    float* out = (float*)d_out;

    float *p_x, *p_t2, *p_p0, *p_p2;
    cudaGetSymbolAddress((void**)&p_x,   g_x);
    cudaGetSymbolAddress((void**)&p_t2,  g_t2);
    cudaGetSymbolAddress((void**)&p_p0,  g_p0);
    cudaGetSymbolAddress((void**)&p_p2,  g_p2);

    __half *ah, *qkvh, *wh, *s1h, *s2h;
    cudaGetSymbolAddress((void**)&ah,   g_ah);
    cudaGetSymbolAddress((void**)&qkvh, g_qkvh);
    cudaGetSymbolAddress((void**)&wh,   g_wh);
    cudaGetSymbolAddress((void**)&s1h,  g_s1h);
    cudaGetSymbolAddress((void**)&s2h,  g_s2h);

    cudaFuncSetAttribute(k_gatein, cudaFuncAttributeMaxDynamicSharedMemorySize, GEMM_SMEM_T1);
    cudaFuncSetAttribute(hmma_gemm<0,2>, cudaFuncAttributeMaxDynamicSharedMemorySize, GEMM_SMEM_T1);
    cudaFuncSetAttribute(hmma_gemm<2,0>, cudaFuncAttributeMaxDynamicSharedMemorySize, GEMM_SMEM_T1);
    cudaFuncSetAttribute(hmma_gemm<1,2>, cudaFuncAttributeMaxDynamicSharedMemorySize, GEMM_SMEM_T1);
    cudaFuncSetAttribute(hmma_gemm<2,2>, cudaFuncAttributeMaxDynamicSharedMemorySize, GEMM_SMEM_T1);
    cudaFuncSetAttribute(hmma_gemm<0,0>, cudaFuncAttributeMaxDynamicSharedMemorySize, GEMM_SMEM_T1);
    cudaFuncSetAttribute(k_pool_f, cudaFuncAttributeMaxDynamicSharedMemorySize, POOLF_SMEM);

    __half *wgh = wh + 0*(size_t)DD_;
    __half *wih = wh + 1*(size_t)DD_;
    __half *wqh = wh + 2*(size_t)DD_;
    __half *wmh = wh + 5*(size_t)DD_;
    __half *wuh = wh + 6*(size_t)DD_;
    __half *wdh = wh + 7*(size_t)DD_;
    __half *woh = wh + 8*(size_t)DD_;

    dim3 gGI (D_ / 64, T_ / BM_G);            // (16, 256) fused gate+in
    dim3 gBig(D_ / BN_G, T_ / BM_G);          // (8, 256)
    dim3 gQkv(3 * D_ / BN_G, T_ / BM_G);      // (24, 256)
    dim3 gSm(D_ / BN_G, P_ / BM_G);           // (8, 16)

    // 0: weight split
    k_split_all<<<dim3(DD_ / 4 / 256, 9), 256>>>(w_gate, w_in, w_qkv, w_intra,
                                                 w_up, w_down, w_out, wh);
    // 1: x1 = rmsnorm(patch + pos) -> hi plane
    k_add_pos_norm_h1<<<T_, 256>>>(patch, pos, ah);
    // 2: fused gated MLP: x = silu(x1@Wg^T) * (x1@Wi^T)
    k_gatein<<<gGI, 256, GEMM_SMEM_T1>>>(D_, D_, ah, wgh, wih, p_x);
    // 3: conv + residual + rmsnorm (fused)
    k_conv_norm<<<P_, 1024>>>(p_x, conv_w, ah);
    // 4-6: attention block
    hmma_gemm<0,2><<<gQkv, 256, GEMM_SMEM_T1>>>(T_, 3 * D_, D_, ah, wqh,
                                                nullptr, nullptr, qkvh);
    k_attn<<<dim3(P_, NH_), 256>>>(qkvh, ah);
    hmma_gemm<2,0><<<gBig, 256, GEMM_SMEM_T1>>>(T_, D_, D_, ah, wmh,
                                                p_x, p_t2, nullptr);
    // 7: fused rmsnorm + pooling
    k_pool_f<<<P_, 256, POOLF_SMEM>>>(p_t2, w_pool, temp, p_p0);
    // 8-12: patch-level MLP + out proj + final norm (all TERMS=1)
    k_rmsnorm_h1<<<P_, 256>>>(p_p0, s1h);
    hmma_gemm<1,2><<<gSm, 256, GEMM_SMEM_T1>>>(P_, D_, D_, s1h, wuh,
                                               nullptr, nullptr, s2h);
    hmma_gemm<2,2><<<gSm, 256, GEMM_SMEM_T1>>>(P_, D_, D_, s2h, wdh,
                                               p_p0, nullptr, s1h);
    hmma_gemm<0,0><<<gSm, 256, GEMM_SMEM_T1>>>(P_, D_, D_, s1h, woh,
                                               nullptr, p_p2, nullptr);
    k_rmsnorm<<<P_, 256>>>(p_p2, out);
}